// round 6
// baseline (speedup 1.0000x reference)
#include <cuda_runtime.h>

// CLIP_AD pooling: patch_tokens [B=512, 225, D=896] f32 -> out [B, 366, 896]:
//   groups   0..168 : mean over 3x3 sliding windows on 15x15 grid (13x13)
//   groups 169..364 : mean over 2x2 sliding windows (14x14)
//   group      365  : mean over all 225 tokens
//
// R5: revert to R3 config (CHUNK=32, TPB=256, plain LDG staging — best at
// 162.5us). Single change: __launch_bounds__(256, 7) so ptxas fits regs for
// 7 CTAs/SM (R3's regs=34 rounded to 40 and capped residency at 6).

#define GRID15 15
#define NTOK   225
#define DIM    896
#define NGRP   366
#define CHUNK  32            // floats per chunk
#define CH4    (CHUNK / 4)   // 8 float4 per chunk
#define NCHUNK (DIM / CHUNK) // 28
#define TPB    256

__device__ __forceinline__ float4 f4add(float4 a, float4 b) {
    return make_float4(a.x + b.x, a.y + b.y, a.z + b.z, a.w + b.w);
}
__device__ __forceinline__ float4 f4scale(float4 a, float s) {
    return make_float4(a.x * s, a.y * s, a.z * s, a.w * s);
}

__global__ __launch_bounds__(TPB, 7) void clip_pool_kernel(
    const float* __restrict__ tok, float* __restrict__ out)
{
    __shared__ float4 s[NTOK * CH4];  // 225 * 8 * 16B = 28800 B

    const int b  = blockIdx.y;
    const int ch = blockIdx.x;
    const int ROW4 = DIM / 4;  // 224 float4 per token row in gmem

    // ---- stage token slice [225, 32 floats] into smem ----
    const float4* g_tok = reinterpret_cast<const float4*>(
        tok + (size_t)b * NTOK * DIM + (size_t)ch * CHUNK);

    #pragma unroll
    for (int i = threadIdx.x; i < NTOK * CH4; i += TPB) {
        int t = i >> 3;
        int c = i & 7;
        s[i] = g_tok[t * ROW4 + c];
    }
    __syncthreads();

    const int col  = threadIdx.x & 7;   // float4 lane within chunk (0..7)
    const int grow = threadIdx.x >> 3;  // task row (0..31)

    float4* g_out = reinterpret_cast<float4*>(
        out + (size_t)b * NGRP * DIM + (size_t)ch * CHUNK);

    if (grow < 13) {
        // ---- 3x3 window outputs, output row = grow ----
        const float4* r0 = s + ((grow    ) * GRID15) * CH4 + col;
        const float4* r1 = s + ((grow + 1) * GRID15) * CH4 + col;
        const float4* r2 = s + ((grow + 2) * GRID15) * CH4 + col;
        // rolling 3-column window of vertical sums
        float4 v0 = f4add(f4add(r0[0 * CH4], r1[0 * CH4]), r2[0 * CH4]);
        float4 v1 = f4add(f4add(r0[1 * CH4], r1[1 * CH4]), r2[1 * CH4]);
        const float inv9 = 1.0f / 9.0f;
        #pragma unroll
        for (int c = 0; c < 13; c++) {
            float4 v2 = f4add(f4add(r0[(c + 2) * CH4], r1[(c + 2) * CH4]),
                              r2[(c + 2) * CH4]);
            float4 res = f4scale(f4add(f4add(v0, v1), v2), inv9);
            g_out[(size_t)(grow * 13 + c) * ROW4 + col] = res;
            v0 = v1; v1 = v2;
        }
    } else if (grow < 27) {
        // ---- 2x2 window outputs, output row = grow - 13 ----
        const int rr = grow - 13;
        const float4* r0 = s + ((rr    ) * GRID15) * CH4 + col;
        const float4* r1 = s + ((rr + 1) * GRID15) * CH4 + col;
        float4 v0 = f4add(r0[0], r1[0]);
        #pragma unroll
        for (int c = 0; c < 14; c++) {
            float4 v1 = f4add(r0[(c + 1) * CH4], r1[(c + 1) * CH4]);
            float4 res = f4scale(f4add(v0, v1), 0.25f);
            g_out[(size_t)(169 + rr * 14 + c) * ROW4 + col] = res;
            v0 = v1;
        }
    } else if (grow >= 28) {
        // ---- class token: grows 28..31 split the 225 tokens 4 ways;
        //      shfl-butterfly combine across the 4 lane-sets of warp 7. ----
        const int sub   = grow - 28;             // 0..3
        const int start = (NTOK * sub) / 4;
        const int end   = (NTOK * (sub + 1)) / 4;
        float4 acc = make_float4(0.f, 0.f, 0.f, 0.f);
        for (int t = start; t < end; t++) {
            float4 v = s[t * CH4 + col];
            acc.x += v.x; acc.y += v.y; acc.z += v.z; acc.w += v.w;
        }
        #pragma unroll
        for (int m = 8; m <= 16; m <<= 1) {
            acc.x += __shfl_xor_sync(0xffffffffu, acc.x, m);
            acc.y += __shfl_xor_sync(0xffffffffu, acc.y, m);
            acc.z += __shfl_xor_sync(0xffffffffu, acc.z, m);
            acc.w += __shfl_xor_sync(0xffffffffu, acc.w, m);
        }
        if (sub == 0) {
            g_out[(size_t)365 * ROW4 + col] = f4scale(acc, 1.0f / 225.0f);
        }
    }
    // grow == 27: idle in phase 2 (helped with staging)
}

extern "C" void kernel_launch(void* const* d_in, const int* in_sizes, int n_in,
                              void* d_out, int out_size)
{
    (void)in_sizes; (void)n_in; (void)out_size;
    const float* tok = (const float*)d_in[0];
    // d_in[1]/d_in[2] (masks) are deterministic sliding-window tables,
    // reproduced arithmetically in-kernel.
    float* out = (float*)d_out;

    dim3 grid(NCHUNK, 512);
    clip_pool_kernel<<<grid, TPB>>>(tok, out);
}

// round 7
// speedup vs baseline: 1.2528x; 1.2528x over previous
#include <cuda_runtime.h>

// CLIP_AD pooling: patch_tokens [B=512, 225, D=896] f32 -> out [B, 366, 896]:
//   groups   0..168 : mean over 3x3 sliding windows on 15x15 grid (13x13)
//   groups 169..364 : mean over 2x2 sliding windows (14x14)
//   group      365  : mean over all 225 tokens
//
// R6: exact R3 config (CHUNK=32, TPB=256, no min-occupancy hint — R5 showed
// forcing occupancy wrecks ptxas load batching / per-warp MLP). Single change:
// stage via cp.async.cg (16B/lane, 128B per 8 lanes -> same wavefront count as
// LDG.128 path) so all staging loads are in flight without register liveness.

#define GRID15 15
#define NTOK   225
#define DIM    896
#define NGRP   366
#define CHUNK  32            // floats per chunk
#define CH4    (CHUNK / 4)   // 8 float4 per chunk
#define NCHUNK (DIM / CHUNK) // 28
#define TPB    256

__device__ __forceinline__ float4 f4add(float4 a, float4 b) {
    return make_float4(a.x + b.x, a.y + b.y, a.z + b.z, a.w + b.w);
}
__device__ __forceinline__ float4 f4scale(float4 a, float s) {
    return make_float4(a.x * s, a.y * s, a.z * s, a.w * s);
}

__global__ __launch_bounds__(TPB) void clip_pool_kernel(
    const float* __restrict__ tok, float* __restrict__ out)
{
    __shared__ float4 s[NTOK * CH4];  // 225 * 8 * 16B = 28800 B

    const int b  = blockIdx.y;
    const int ch = blockIdx.x;
    const int ROW4 = DIM / 4;  // 224 float4 per token row in gmem

    // ---- stage token slice [225, 32 floats] into smem via cp.async ----
    const float4* g_tok = reinterpret_cast<const float4*>(
        tok + (size_t)b * NTOK * DIM + (size_t)ch * CHUNK);
    unsigned s_base = (unsigned)__cvta_generic_to_shared(s);

    #pragma unroll
    for (int i = threadIdx.x; i < NTOK * CH4; i += TPB) {
        int t = i >> 3;            // token
        int c = i & 7;             // float4 within chunk
        unsigned dst = s_base + (unsigned)i * 16u;
        const float4* src = g_tok + t * ROW4 + c;
        asm volatile("cp.async.cg.shared.global [%0], [%1], 16;\n"
                     :: "r"(dst), "l"(src));
    }
    asm volatile("cp.async.commit_group;\n" ::: "memory");
    asm volatile("cp.async.wait_group 0;\n" ::: "memory");
    __syncthreads();

    const int col  = threadIdx.x & 7;   // float4 lane within chunk (0..7)
    const int grow = threadIdx.x >> 3;  // task row (0..31)

    float4* g_out = reinterpret_cast<float4*>(
        out + (size_t)b * NGRP * DIM + (size_t)ch * CHUNK);

    if (grow < 13) {
        // ---- 3x3 window outputs, output row = grow ----
        const float4* r0 = s + ((grow    ) * GRID15) * CH4 + col;
        const float4* r1 = s + ((grow + 1) * GRID15) * CH4 + col;
        const float4* r2 = s + ((grow + 2) * GRID15) * CH4 + col;
        // rolling 3-column window of vertical sums
        float4 v0 = f4add(f4add(r0[0 * CH4], r1[0 * CH4]), r2[0 * CH4]);
        float4 v1 = f4add(f4add(r0[1 * CH4], r1[1 * CH4]), r2[1 * CH4]);
        const float inv9 = 1.0f / 9.0f;
        #pragma unroll
        for (int c = 0; c < 13; c++) {
            float4 v2 = f4add(f4add(r0[(c + 2) * CH4], r1[(c + 2) * CH4]),
                              r2[(c + 2) * CH4]);
            float4 res = f4scale(f4add(f4add(v0, v1), v2), inv9);
            g_out[(size_t)(grow * 13 + c) * ROW4 + col] = res;
            v0 = v1; v1 = v2;
        }
    } else if (grow < 27) {
        // ---- 2x2 window outputs, output row = grow - 13 ----
        const int rr = grow - 13;
        const float4* r0 = s + ((rr    ) * GRID15) * CH4 + col;
        const float4* r1 = s + ((rr + 1) * GRID15) * CH4 + col;
        float4 v0 = f4add(r0[0], r1[0]);
        #pragma unroll
        for (int c = 0; c < 14; c++) {
            float4 v1 = f4add(r0[(c + 1) * CH4], r1[(c + 1) * CH4]);
            float4 res = f4scale(f4add(v0, v1), 0.25f);
            g_out[(size_t)(169 + rr * 14 + c) * ROW4 + col] = res;
            v0 = v1;
        }
    } else if (grow >= 28) {
        // ---- class token: grows 28..31 split the 225 tokens 4 ways;
        //      shfl-butterfly combine across the 4 lane-sets of warp 7. ----
        const int sub   = grow - 28;             // 0..3
        const int start = (NTOK * sub) / 4;
        const int end   = (NTOK * (sub + 1)) / 4;
        float4 acc = make_float4(0.f, 0.f, 0.f, 0.f);
        for (int t = start; t < end; t++) {
            float4 v = s[t * CH4 + col];
            acc.x += v.x; acc.y += v.y; acc.z += v.z; acc.w += v.w;
        }
        #pragma unroll
        for (int m = 8; m <= 16; m <<= 1) {
            acc.x += __shfl_xor_sync(0xffffffffu, acc.x, m);
            acc.y += __shfl_xor_sync(0xffffffffu, acc.y, m);
            acc.z += __shfl_xor_sync(0xffffffffu, acc.z, m);
            acc.w += __shfl_xor_sync(0xffffffffu, acc.w, m);
        }
        if (sub == 0) {
            g_out[(size_t)365 * ROW4 + col] = f4scale(acc, 1.0f / 225.0f);
        }
    }
    // grow == 27: idle in phase 2 (helped with staging)
}

extern "C" void kernel_launch(void* const* d_in, const int* in_sizes, int n_in,
                              void* d_out, int out_size)
{
    (void)in_sizes; (void)n_in; (void)out_size;
    const float* tok = (const float*)d_in[0];
    // d_in[1]/d_in[2] (masks) are deterministic sliding-window tables,
    // reproduced arithmetically in-kernel.
    float* out = (float*)d_out;

    dim3 grid(NCHUNK, 512);
    clip_pool_kernel<<<grid, TPB>>>(tok, out);
}